// round 8
// baseline (speedup 1.0000x reference)
#include <cuda_runtime.h>
#include <cuda_bf16.h>
#include <math.h>
#include <stdint.h>

#define LL 1024
#define BB 128
#define DD 256
#define HH 256

#define XN (LL * BB * DD)
#define WN (HH * DD)

// Pre-split bf16 scratch (static device arrays — allowed)
__device__ __align__(16) __nv_bfloat16 g_xhi[XN];
__device__ __align__(16) __nv_bfloat16 g_xlo[XN];
__device__ __align__(16) __nv_bfloat16 g_whi[WN];
__device__ __align__(16) __nv_bfloat16 g_wlo[WN];

__device__ __forceinline__ uint32_t smem_u32(const void* p) {
    uint32_t a;
    asm("{ .reg .u64 t; cvta.to.shared.u64 t, %1; cvt.u32.u64 %0, t; }"
        : "=r"(a) : "l"(p));
    return a;
}

__device__ __forceinline__ void split2(float a, float b, uint32_t& h, uint32_t& l) {
    __nv_bfloat16 ha = __float2bfloat16(a);
    __nv_bfloat16 hb = __float2bfloat16(b);
    float ra = a - __bfloat162float(ha);
    float rb = b - __bfloat162float(hb);
    __nv_bfloat16 la = __float2bfloat16(ra);
    __nv_bfloat16 lb = __float2bfloat16(rb);
    h = (uint32_t)reinterpret_cast<unsigned short&>(ha) |
        ((uint32_t)reinterpret_cast<unsigned short&>(hb) << 16);
    l = (uint32_t)reinterpret_cast<unsigned short&>(la) |
        ((uint32_t)reinterpret_cast<unsigned short&>(lb) << 16);
}

// ====================================================================
// Kernel 0: one-shot fp32 -> split-bf16 (hi, lo) for X and Wx.
// ====================================================================
#define CV_JOBS ((XN + WN) / 4)

__global__ __launch_bounds__(256) void convert_kernel(
    const float* __restrict__ X, const float* __restrict__ Wx)
{
    int i = blockIdx.x * 256 + threadIdx.x;
    if (i >= CV_JOBS) return;
    float4 v;
    if (i < XN / 4) v = ((const float4*)X)[i];
    else            v = ((const float4*)Wx)[i - XN / 4];
    uint2 hi, lo;
    split2(v.x, v.y, hi.x, lo.x);
    split2(v.z, v.w, hi.y, lo.y);
    if (i < XN / 4) {
        *(uint2*)(g_xhi + (size_t)i * 4) = hi;
        *(uint2*)(g_xlo + (size_t)i * 4) = lo;
    } else {
        size_t o = (size_t)(i - XN / 4) * 4;
        *(uint2*)(g_whi + o) = hi;
        *(uint2*)(g_wlo + o) = lo;
    }
}

// ====================================================================
// Kernel 1: xproj GEMM via mma.sync bf16 split-3, fp32 accum (unchanged).
// ====================================================================
#define XP_STRIDE_B 144
#define XP_TILE_B   (128 * XP_STRIDE_B)
#define XP_AHI 0
#define XP_ALO XP_TILE_B
#define XP_WHI (2 * XP_TILE_B)
#define XP_WLO (3 * XP_TILE_B)
#define XP_SMEM (4 * XP_TILE_B)

__device__ __forceinline__ void ldm_x4(uint32_t& r0, uint32_t& r1,
                                       uint32_t& r2, uint32_t& r3, uint32_t addr) {
    asm volatile("ldmatrix.sync.aligned.m8n8.x4.shared.b16 {%0,%1,%2,%3}, [%4];"
                 : "=r"(r0), "=r"(r1), "=r"(r2), "=r"(r3) : "r"(addr));
}

__device__ __forceinline__ void mma16816(float* c, const uint32_t* a,
                                         uint32_t b0, uint32_t b1) {
    asm volatile(
        "mma.sync.aligned.m16n8k16.row.col.f32.bf16.bf16.f32 "
        "{%0,%1,%2,%3}, {%4,%5,%6,%7}, {%8,%9}, {%0,%1,%2,%3};"
        : "+f"(c[0]), "+f"(c[1]), "+f"(c[2]), "+f"(c[3])
        : "r"(a[0]), "r"(a[1]), "r"(a[2]), "r"(a[3]), "r"(b0), "r"(b1));
}

__global__ __launch_bounds__(256) void xproj_mma_kernel(
    const float* __restrict__ bx,
    float* __restrict__ C)
{
    extern __shared__ char smem[];
    const uint32_t sb = smem_u32(smem);
    const int tid = threadIdx.x;
    const int wid = tid >> 5;
    const int l   = tid & 31;
    const int warp_m = wid & 3;
    const int warp_n = wid >> 2;
    const int m0 = blockIdx.x * 128;
    const int n0 = blockIdx.y * 128;

    float acc[2][8][4];
#pragma unroll
    for (int t = 0; t < 2; t++)
#pragma unroll
        for (int nb = 0; nb < 8; nb++)
#pragma unroll
            for (int i = 0; i < 4; i++) acc[t][nb][i] = 0.0f;

    const uint32_t aRowOff = (uint32_t)((warp_m * 32 + (l & 15)) * XP_STRIDE_B +
                                        (l >> 4) * 16);
    const uint32_t bRowOff = (uint32_t)((warp_n * 64 + ((l >> 4) << 3) + (l & 7)) * XP_STRIDE_B +
                                        ((l >> 3) & 1) * 16);

    for (int c = 0; c < 4; ++c) {
        const int k0 = c * 64;
#pragma unroll
        for (int q = 0; q < 4; ++q) {
            int job = q * 256 + tid;
            int row = job >> 3, kg = job & 7;
            size_t src = (size_t)(m0 + row) * DD + k0 + kg * 8;
            int off = row * XP_STRIDE_B + kg * 16;
            *(uint4*)(smem + XP_AHI + off) = *(const uint4*)(g_xhi + src);
            *(uint4*)(smem + XP_ALO + off) = *(const uint4*)(g_xlo + src);
        }
#pragma unroll
        for (int q = 0; q < 4; ++q) {
            int job = q * 256 + tid;
            int row = job >> 3, kg = job & 7;
            size_t src = (size_t)(n0 + row) * DD + k0 + kg * 8;
            int off = row * XP_STRIDE_B + kg * 16;
            *(uint4*)(smem + XP_WHI + off) = *(const uint4*)(g_whi + src);
            *(uint4*)(smem + XP_WLO + off) = *(const uint4*)(g_wlo + src);
        }
        __syncthreads();

#pragma unroll
        for (int ks = 0; ks < 4; ++ks) {
            const uint32_t kOff = (uint32_t)(ks * 32);
            uint32_t ahi[2][4], alo[2][4];
#pragma unroll
            for (int t = 0; t < 2; t++) {
                uint32_t abase = aRowOff + (uint32_t)(t * 16 * XP_STRIDE_B) + kOff;
                ldm_x4(ahi[t][0], ahi[t][1], ahi[t][2], ahi[t][3], sb + XP_AHI + abase);
                ldm_x4(alo[t][0], alo[t][1], alo[t][2], alo[t][3], sb + XP_ALO + abase);
            }
#pragma unroll
            for (int g = 0; g < 4; ++g) {
                uint32_t bbase = bRowOff + (uint32_t)(g * 16 * XP_STRIDE_B) + kOff;
                uint32_t h0, h1, h2, h3, q0, q1, q2, q3;
                ldm_x4(h0, h1, h2, h3, sb + XP_WHI + bbase);
                ldm_x4(q0, q1, q2, q3, sb + XP_WLO + bbase);
#pragma unroll
                for (int t = 0; t < 2; t++) {
                    mma16816(acc[t][2 * g],     ahi[t], h0, h1);
                    mma16816(acc[t][2 * g + 1], ahi[t], h2, h3);
                    mma16816(acc[t][2 * g],     alo[t], h0, h1);
                    mma16816(acc[t][2 * g + 1], alo[t], h2, h3);
                    mma16816(acc[t][2 * g],     ahi[t], q0, q1);
                    mma16816(acc[t][2 * g + 1], ahi[t], q2, q3);
                }
            }
        }
        __syncthreads();
    }

    const int mrow = m0 + warp_m * 32 + (l >> 2);
    const int ncol = n0 + warp_n * 64 + 2 * (l & 3);
#pragma unroll
    for (int t = 0; t < 2; t++) {
#pragma unroll
        for (int nb = 0; nb < 8; nb++) {
            int nn = ncol + nb * 8;
            float2 bv = *(const float2*)(bx + nn);
            int r0 = mrow + t * 16;
            float2 o0 = make_float2(acc[t][nb][0] + bv.x, acc[t][nb][1] + bv.y);
            float2 o1 = make_float2(acc[t][nb][2] + bv.x, acc[t][nb][3] + bv.y);
            *(float2*)(C + (size_t)r0 * HH + nn) = o0;
            *(float2*)(C + (size_t)(r0 + 8) * HH + nn) = o1;
        }
    }
}

// ====================================================================
// Kernel 2: scan v3 — lane-paired halves, shuffle combine, 1 barrier/step.
//   lane 2i   -> neuron j = wid*16+i, k in [0,128)
//   lane 2i+1 -> same neuron,          k in [128,256)
//   partial sums combined via shfl.xor(1); both lanes compute tanh;
//   even lane writes smem h (ping-pong), odd lane writes global out.
// ====================================================================
__global__ __launch_bounds__(512, 1) void scan_kernel(
    const float* __restrict__ h0,
    const float* __restrict__ Wh,
    const float* __restrict__ bh,
    float* __restrict__ out,
    int hasFinal)
{
    extern __shared__ float smemf[];
    float4* Wsm  = (float4*)smemf;           // [8][512] float4 = 64 KB
    float*  hbuf = smemf + 8 * 512 * 4;      // 2*256 floats (ping-pong)

    const int tid  = threadIdx.x;
    const int wid  = tid >> 5;
    const int l    = tid & 31;
    const int j    = wid * 16 + (l >> 1);
    const int half = l & 1;
    const int kb   = half * 128;
    const int b    = blockIdx.x;

    // weights for (j, k-half): 96 in registers + 32 in smem
    float4 wr[24];
    const float4* wrow = (const float4*)(Wh + (size_t)j * HH + kb);
#pragma unroll
    for (int i = 0; i < 24; i++) wr[i] = wrow[i];
#pragma unroll
    for (int g = 0; g < 8; ++g)
        Wsm[g * 512 + tid] = wrow[24 + g];

    if (tid < 256) hbuf[tid] = h0[(size_t)b * HH + tid];
    const float bh_r = bh[j];
    float* const xpp = out + (size_t)b * HH + j;   // step stride BB*HH
    __syncthreads();

    int cur = 0;
    for (int t = 0; t < LL; ++t) {
        // xp issued early; ~170 instructions of slack before use
        const float xp = xpp[(size_t)t * (BB * HH)];

        const float4* h4 = (const float4*)(hbuf + cur * 256 + kb);
        float a0 = 0.f, a1 = 0.f, a2 = 0.f, a3 = 0.f;
#pragma unroll
        for (int i = 0; i < 24; i++) {
            float4 hv = h4[i];
            a0 = fmaf(wr[i].x, hv.x, a0);
            a1 = fmaf(wr[i].y, hv.y, a1);
            a2 = fmaf(wr[i].z, hv.z, a2);
            a3 = fmaf(wr[i].w, hv.w, a3);
        }
#pragma unroll
        for (int g = 0; g < 8; g++) {
            float4 wv = Wsm[g * 512 + tid];
            float4 hv = h4[24 + g];
            a0 = fmaf(wv.x, hv.x, a0);
            a1 = fmaf(wv.y, hv.y, a1);
            a2 = fmaf(wv.z, hv.z, a2);
            a3 = fmaf(wv.w, hv.w, a3);
        }
        float acc = (a0 + a1) + (a2 + a3);
        float other = __shfl_xor_sync(0xFFFFFFFFu, acc, 1);
        float hn = tanhf(acc + other + xp + bh_r);

        if (half == 0) {
            hbuf[(cur ^ 1) * 256 + j] = hn;
            if (hasFinal && t == LL - 1)
                xpp[(size_t)LL * (BB * HH)] = hn;     // final state
        } else {
            xpp[(size_t)t * (BB * HH)] = hn;          // hAll[t]
        }
        __syncthreads();
        cur ^= 1;
    }
}

// ====================================================================
// launch
// ====================================================================
extern "C" void kernel_launch(void* const* d_in, const int* in_sizes, int n_in,
                              void* d_out, int out_size)
{
    const float* x   = (const float*)d_in[0];
    const float* h0  = (const float*)d_in[1];
    const float* Wxw = (const float*)d_in[2];
    const float* Wxb = (const float*)d_in[3];
    const float* Whw = (const float*)d_in[4];
    const float* Whb = (const float*)d_in[5];
    float* out = (float*)d_out;

    (void)in_sizes; (void)n_in;

    cudaFuncSetAttribute(xproj_mma_kernel, cudaFuncAttributeMaxDynamicSharedMemorySize, XP_SMEM);
    const int smemScan = (8 * 512 * 4 + 512) * (int)sizeof(float);   // 67584
    cudaFuncSetAttribute(scan_kernel, cudaFuncAttributeMaxDynamicSharedMemorySize, smemScan);

    convert_kernel<<<(CV_JOBS + 255) / 256, 256>>>(x, Wxw);

    dim3 g1(LL * BB / 128, HH / 128);   // (1024, 2)
    xproj_mma_kernel<<<g1, 256, XP_SMEM>>>(Wxb, out);

    const int hasFinal = (out_size >= LL * BB * HH + BB * HH) ? 1 : 0;
    scan_kernel<<<BB, 512, smemScan>>>(h0, Whw, Whb, out, hasFinal);
}

// round 9
// speedup vs baseline: 1.4214x; 1.4214x over previous
#include <cuda_runtime.h>
#include <cuda_bf16.h>
#include <math.h>
#include <stdint.h>

#define LL 1024
#define BB 128
#define DD 256
#define HH 256

#define XN (LL * BB * DD)
#define WN (HH * DD)

// Pre-split bf16 scratch (static device arrays — allowed)
__device__ __align__(16) __nv_bfloat16 g_xhi[XN];
__device__ __align__(16) __nv_bfloat16 g_xlo[XN];
__device__ __align__(16) __nv_bfloat16 g_whi[WN];
__device__ __align__(16) __nv_bfloat16 g_wlo[WN];

__device__ __forceinline__ uint32_t smem_u32(const void* p) {
    uint32_t a;
    asm("{ .reg .u64 t; cvta.to.shared.u64 t, %1; cvt.u32.u64 %0, t; }"
        : "=r"(a) : "l"(p));
    return a;
}

// Packed f32x2 FMA
__device__ __forceinline__ unsigned long long ffma2(
    unsigned long long a, unsigned long long b, unsigned long long c)
{
    unsigned long long d;
    asm("fma.rn.f32x2 %0, %1, %2, %3;" : "=l"(d) : "l"(a), "l"(b), "l"(c));
    return d;
}
__device__ __forceinline__ float upk_sum(unsigned long long p)
{
    float lo, hi;
    asm("mov.b64 {%0, %1}, %2;" : "=f"(lo), "=f"(hi) : "l"(p));
    return lo + hi;
}

__device__ __forceinline__ void split2(float a, float b, uint32_t& h, uint32_t& l) {
    __nv_bfloat16 ha = __float2bfloat16(a);
    __nv_bfloat16 hb = __float2bfloat16(b);
    float ra = a - __bfloat162float(ha);
    float rb = b - __bfloat162float(hb);
    __nv_bfloat16 la = __float2bfloat16(ra);
    __nv_bfloat16 lb = __float2bfloat16(rb);
    h = (uint32_t)reinterpret_cast<unsigned short&>(ha) |
        ((uint32_t)reinterpret_cast<unsigned short&>(hb) << 16);
    l = (uint32_t)reinterpret_cast<unsigned short&>(la) |
        ((uint32_t)reinterpret_cast<unsigned short&>(lb) << 16);
}

// ====================================================================
// Kernel 0: one-shot fp32 -> split-bf16 (hi, lo) for X and Wx.
// ====================================================================
#define CV_JOBS ((XN + WN) / 4)

__global__ __launch_bounds__(256) void convert_kernel(
    const float* __restrict__ X, const float* __restrict__ Wx)
{
    int i = blockIdx.x * 256 + threadIdx.x;
    if (i >= CV_JOBS) return;
    float4 v;
    if (i < XN / 4) v = ((const float4*)X)[i];
    else            v = ((const float4*)Wx)[i - XN / 4];
    uint2 hi, lo;
    split2(v.x, v.y, hi.x, lo.x);
    split2(v.z, v.w, hi.y, lo.y);
    if (i < XN / 4) {
        *(uint2*)(g_xhi + (size_t)i * 4) = hi;
        *(uint2*)(g_xlo + (size_t)i * 4) = lo;
    } else {
        size_t o = (size_t)(i - XN / 4) * 4;
        *(uint2*)(g_whi + o) = hi;
        *(uint2*)(g_wlo + o) = lo;
    }
}

// ====================================================================
// Kernel 1: xproj GEMM via mma.sync bf16 split-3, fp32 accum (unchanged).
// ====================================================================
#define XP_STRIDE_B 144
#define XP_TILE_B   (128 * XP_STRIDE_B)
#define XP_AHI 0
#define XP_ALO XP_TILE_B
#define XP_WHI (2 * XP_TILE_B)
#define XP_WLO (3 * XP_TILE_B)
#define XP_SMEM (4 * XP_TILE_B)

__device__ __forceinline__ void ldm_x4(uint32_t& r0, uint32_t& r1,
                                       uint32_t& r2, uint32_t& r3, uint32_t addr) {
    asm volatile("ldmatrix.sync.aligned.m8n8.x4.shared.b16 {%0,%1,%2,%3}, [%4];"
                 : "=r"(r0), "=r"(r1), "=r"(r2), "=r"(r3) : "r"(addr));
}

__device__ __forceinline__ void mma16816(float* c, const uint32_t* a,
                                         uint32_t b0, uint32_t b1) {
    asm volatile(
        "mma.sync.aligned.m16n8k16.row.col.f32.bf16.bf16.f32 "
        "{%0,%1,%2,%3}, {%4,%5,%6,%7}, {%8,%9}, {%0,%1,%2,%3};"
        : "+f"(c[0]), "+f"(c[1]), "+f"(c[2]), "+f"(c[3])
        : "r"(a[0]), "r"(a[1]), "r"(a[2]), "r"(a[3]), "r"(b0), "r"(b1));
}

__global__ __launch_bounds__(256) void xproj_mma_kernel(
    const float* __restrict__ bx,
    float* __restrict__ C)
{
    extern __shared__ char smem[];
    const uint32_t sb = smem_u32(smem);
    const int tid = threadIdx.x;
    const int wid = tid >> 5;
    const int l   = tid & 31;
    const int warp_m = wid & 3;
    const int warp_n = wid >> 2;
    const int m0 = blockIdx.x * 128;
    const int n0 = blockIdx.y * 128;

    float acc[2][8][4];
#pragma unroll
    for (int t = 0; t < 2; t++)
#pragma unroll
        for (int nb = 0; nb < 8; nb++)
#pragma unroll
            for (int i = 0; i < 4; i++) acc[t][nb][i] = 0.0f;

    const uint32_t aRowOff = (uint32_t)((warp_m * 32 + (l & 15)) * XP_STRIDE_B +
                                        (l >> 4) * 16);
    const uint32_t bRowOff = (uint32_t)((warp_n * 64 + ((l >> 4) << 3) + (l & 7)) * XP_STRIDE_B +
                                        ((l >> 3) & 1) * 16);

    for (int c = 0; c < 4; ++c) {
        const int k0 = c * 64;
#pragma unroll
        for (int q = 0; q < 4; ++q) {
            int job = q * 256 + tid;
            int row = job >> 3, kg = job & 7;
            size_t src = (size_t)(m0 + row) * DD + k0 + kg * 8;
            int off = row * XP_STRIDE_B + kg * 16;
            *(uint4*)(smem + XP_AHI + off) = *(const uint4*)(g_xhi + src);
            *(uint4*)(smem + XP_ALO + off) = *(const uint4*)(g_xlo + src);
        }
#pragma unroll
        for (int q = 0; q < 4; ++q) {
            int job = q * 256 + tid;
            int row = job >> 3, kg = job & 7;
            size_t src = (size_t)(n0 + row) * DD + k0 + kg * 8;
            int off = row * XP_STRIDE_B + kg * 16;
            *(uint4*)(smem + XP_WHI + off) = *(const uint4*)(g_whi + src);
            *(uint4*)(smem + XP_WLO + off) = *(const uint4*)(g_wlo + src);
        }
        __syncthreads();

#pragma unroll
        for (int ks = 0; ks < 4; ++ks) {
            const uint32_t kOff = (uint32_t)(ks * 32);
            uint32_t ahi[2][4], alo[2][4];
#pragma unroll
            for (int t = 0; t < 2; t++) {
                uint32_t abase = aRowOff + (uint32_t)(t * 16 * XP_STRIDE_B) + kOff;
                ldm_x4(ahi[t][0], ahi[t][1], ahi[t][2], ahi[t][3], sb + XP_AHI + abase);
                ldm_x4(alo[t][0], alo[t][1], alo[t][2], alo[t][3], sb + XP_ALO + abase);
            }
#pragma unroll
            for (int g = 0; g < 4; ++g) {
                uint32_t bbase = bRowOff + (uint32_t)(g * 16 * XP_STRIDE_B) + kOff;
                uint32_t h0, h1, h2, h3, q0, q1, q2, q3;
                ldm_x4(h0, h1, h2, h3, sb + XP_WHI + bbase);
                ldm_x4(q0, q1, q2, q3, sb + XP_WLO + bbase);
#pragma unroll
                for (int t = 0; t < 2; t++) {
                    mma16816(acc[t][2 * g],     ahi[t], h0, h1);
                    mma16816(acc[t][2 * g + 1], ahi[t], h2, h3);
                    mma16816(acc[t][2 * g],     alo[t], h0, h1);
                    mma16816(acc[t][2 * g + 1], alo[t], h2, h3);
                    mma16816(acc[t][2 * g],     ahi[t], q0, q1);
                    mma16816(acc[t][2 * g + 1], ahi[t], q2, q3);
                }
            }
        }
        __syncthreads();
    }

    const int mrow = m0 + warp_m * 32 + (l >> 2);
    const int ncol = n0 + warp_n * 64 + 2 * (l & 3);
#pragma unroll
    for (int t = 0; t < 2; t++) {
#pragma unroll
        for (int nb = 0; nb < 8; nb++) {
            int nn = ncol + nb * 8;
            float2 bv = *(const float2*)(bx + nn);
            int r0 = mrow + t * 16;
            float2 o0 = make_float2(acc[t][nb][0] + bv.x, acc[t][nb][1] + bv.y);
            float2 o1 = make_float2(acc[t][nb][2] + bv.x, acc[t][nb][3] + bv.y);
            *(float2*)(C + (size_t)r0 * HH + nn) = o0;
            *(float2*)(C + (size_t)(r0 + 8) * HH + nn) = o1;
        }
    }
}

// ====================================================================
// Kernel 2: scan v4 — R4 half-split structure +
//   (a) f32x2 packed FMA, (b) xp one-step prefetch,
//   (c) symmetric finalize via dual part buffers (split stores).
// Thread (j = tid&255, half = tid>>8), k in [half*128, half*128+128).
// 96 k-weights in registers (24 ulonglong2), 32 in smem.
// ====================================================================
__global__ __launch_bounds__(512, 1) void scan_kernel(
    const float* __restrict__ h0,
    const float* __restrict__ Wh,
    const float* __restrict__ bh,
    float* __restrict__ out,
    int hasFinal)
{
    extern __shared__ float smemf[];
    float4* Ws4   = (float4*)smemf;          // 16*256 float4 = 64 KB
    float*  hbuf  = smemf + 16 * 256 * 4;    // 512 (ping-pong)
    float*  partA = hbuf + 512;              // 256: written by half1, read by half0
    float*  partB = partA + 256;             // 256: written by half0, read by half1

    const int tid  = threadIdx.x;
    const int j    = tid & 255;
    const int half = tid >> 8;
    const int b    = blockIdx.x;
    const int kb   = half * 128;

    // register-resident weights: k in [kb, kb+96) as 48 packed f32x2 pairs
    ulonglong2 wu[24];
    const ulonglong2* wrow = (const ulonglong2*)(Wh + (size_t)j * HH + kb);
#pragma unroll
    for (int i = 0; i < 24; i++) wu[i] = wrow[i];

    // shared weights: g<8 -> k = 96+4g (half 0), g>=8 -> k = 224+4(g-8) (half 1)
    for (int idx = tid; idx < 16 * 256; idx += 512) {
        int g  = idx >> 8;
        int jj = idx & 255;
        int kk = (g < 8) ? (96 + 4 * g) : (224 + 4 * (g - 8));
        Ws4[g * 256 + jj] = *(const float4*)(Wh + (size_t)jj * HH + kk);
    }
    if (tid < 256) hbuf[tid] = h0[(size_t)b * HH + tid];

    const float bh_r = bh[j];
    float* const outp = out + (size_t)b * HH + j;   // step stride BB*HH

    // prefetch xp for t=0 (all threads: both halves compute tanh)
    float xp_next = outp[0];
    __syncthreads();

    const ulonglong2* ws2base = (const ulonglong2*)Ws4 + (size_t)(half * 8) * 256 + j;

    int cur = 0;
    for (int t = 0; t < LL; ++t) {
        const float xp = xp_next;
        if (t + 1 < LL) xp_next = outp[(size_t)(t + 1) * (BB * HH)];

        const ulonglong2* h2 = (const ulonglong2*)(hbuf + cur * 256 + kb);
        unsigned long long p0 = 0ULL, p1 = 0ULL, p2 = 0ULL, p3 = 0ULL;
#pragma unroll
        for (int i = 0; i < 24; i++) {
            ulonglong2 hv = h2[i];
            p0 = ffma2(wu[i].x, hv.x, p0);
            p1 = ffma2(wu[i].y, hv.y, p1);
        }
#pragma unroll
        for (int g = 0; g < 8; g++) {
            ulonglong2 wv = ws2base[(size_t)g * 256];
            ulonglong2 hv = h2[24 + g];
            p2 = ffma2(wv.x, hv.x, p2);
            p3 = ffma2(wv.y, hv.y, p3);
        }
        float acc = (upk_sum(p0) + upk_sum(p1)) + (upk_sum(p2) + upk_sum(p3));

        if (half) partA[j] = acc;
        else      partB[j] = acc;
        __syncthreads();

        const float other = half ? partB[j] : partA[j];
        const float hn = tanhf(acc + other + xp + bh_r);

        if (!half) {
            hbuf[(cur ^ 1) * 256 + j] = hn;
        } else {
            outp[(size_t)t * (BB * HH)] = hn;
            if (hasFinal && t == LL - 1)
                outp[(size_t)LL * (BB * HH)] = hn;
        }
        __syncthreads();
        cur ^= 1;
    }
}

// ====================================================================
// launch
// ====================================================================
extern "C" void kernel_launch(void* const* d_in, const int* in_sizes, int n_in,
                              void* d_out, int out_size)
{
    const float* x   = (const float*)d_in[0];
    const float* h0  = (const float*)d_in[1];
    const float* Wxw = (const float*)d_in[2];
    const float* Wxb = (const float*)d_in[3];
    const float* Whw = (const float*)d_in[4];
    const float* Whb = (const float*)d_in[5];
    float* out = (float*)d_out;

    (void)in_sizes; (void)n_in;

    cudaFuncSetAttribute(xproj_mma_kernel, cudaFuncAttributeMaxDynamicSharedMemorySize, XP_SMEM);
    const int smemScan = (16 * 256 * 4 + 512 + 256 + 256) * (int)sizeof(float);
    cudaFuncSetAttribute(scan_kernel, cudaFuncAttributeMaxDynamicSharedMemorySize, smemScan);

    convert_kernel<<<(CV_JOBS + 255) / 256, 256>>>(x, Wxw);

    dim3 g1(LL * BB / 128, HH / 128);   // (1024, 2)
    xproj_mma_kernel<<<g1, 256, XP_SMEM>>>(Wxb, out);

    const int hasFinal = (out_size >= LL * BB * HH + BB * HH) ? 1 : 0;
    scan_kernel<<<BB, 512, smemScan>>>(h0, Whw, Whb, out, hasFinal);
}

// round 10
// speedup vs baseline: 1.4581x; 1.0258x over previous
#include <cuda_runtime.h>
#include <cuda_bf16.h>
#include <math.h>
#include <stdint.h>

#define LL 1024
#define BB 128
#define DD 256
#define HH 256

#define XN (LL * BB * DD)
#define WN (HH * DD)

// Pre-split bf16 scratch (static device arrays — allowed)
__device__ __align__(16) __nv_bfloat16 g_xhi[XN];
__device__ __align__(16) __nv_bfloat16 g_xlo[XN];
__device__ __align__(16) __nv_bfloat16 g_whi[WN];
__device__ __align__(16) __nv_bfloat16 g_wlo[WN];

__device__ __forceinline__ uint32_t smem_u32(const void* p) {
    uint32_t a;
    asm("{ .reg .u64 t; cvta.to.shared.u64 t, %1; cvt.u32.u64 %0, t; }"
        : "=r"(a) : "l"(p));
    return a;
}

// Packed f32x2 FMA
__device__ __forceinline__ unsigned long long ffma2(
    unsigned long long a, unsigned long long b, unsigned long long c)
{
    unsigned long long d;
    asm("fma.rn.f32x2 %0, %1, %2, %3;" : "=l"(d) : "l"(a), "l"(b), "l"(c));
    return d;
}
__device__ __forceinline__ float upk_sum(unsigned long long p)
{
    float lo, hi;
    asm("mov.b64 {%0, %1}, %2;" : "=f"(lo), "=f"(hi) : "l"(p));
    return lo + hi;
}

__device__ __forceinline__ void split2(float a, float b, uint32_t& h, uint32_t& l) {
    __nv_bfloat16 ha = __float2bfloat16(a);
    __nv_bfloat16 hb = __float2bfloat16(b);
    float ra = a - __bfloat162float(ha);
    float rb = b - __bfloat162float(hb);
    __nv_bfloat16 la = __float2bfloat16(ra);
    __nv_bfloat16 lb = __float2bfloat16(rb);
    h = (uint32_t)reinterpret_cast<unsigned short&>(ha) |
        ((uint32_t)reinterpret_cast<unsigned short&>(hb) << 16);
    l = (uint32_t)reinterpret_cast<unsigned short&>(la) |
        ((uint32_t)reinterpret_cast<unsigned short&>(lb) << 16);
}

// ====================================================================
// Kernel 0: one-shot fp32 -> split-bf16 (hi, lo) for X and Wx.
// ====================================================================
#define CV_JOBS ((XN + WN) / 4)

__global__ __launch_bounds__(256) void convert_kernel(
    const float* __restrict__ X, const float* __restrict__ Wx)
{
    int i = blockIdx.x * 256 + threadIdx.x;
    if (i >= CV_JOBS) return;
    float4 v;
    if (i < XN / 4) v = ((const float4*)X)[i];
    else            v = ((const float4*)Wx)[i - XN / 4];
    uint2 hi, lo;
    split2(v.x, v.y, hi.x, lo.x);
    split2(v.z, v.w, hi.y, lo.y);
    if (i < XN / 4) {
        *(uint2*)(g_xhi + (size_t)i * 4) = hi;
        *(uint2*)(g_xlo + (size_t)i * 4) = lo;
    } else {
        size_t o = (size_t)(i - XN / 4) * 4;
        *(uint2*)(g_whi + o) = hi;
        *(uint2*)(g_wlo + o) = lo;
    }
}

// ====================================================================
// Kernel 1: xproj GEMM via mma.sync bf16 split-3, fp32 accum (unchanged).
// ====================================================================
#define XP_STRIDE_B 144
#define XP_TILE_B   (128 * XP_STRIDE_B)
#define XP_AHI 0
#define XP_ALO XP_TILE_B
#define XP_WHI (2 * XP_TILE_B)
#define XP_WLO (3 * XP_TILE_B)
#define XP_SMEM (4 * XP_TILE_B)

__device__ __forceinline__ void ldm_x4(uint32_t& r0, uint32_t& r1,
                                       uint32_t& r2, uint32_t& r3, uint32_t addr) {
    asm volatile("ldmatrix.sync.aligned.m8n8.x4.shared.b16 {%0,%1,%2,%3}, [%4];"
                 : "=r"(r0), "=r"(r1), "=r"(r2), "=r"(r3) : "r"(addr));
}

__device__ __forceinline__ void mma16816(float* c, const uint32_t* a,
                                         uint32_t b0, uint32_t b1) {
    asm volatile(
        "mma.sync.aligned.m16n8k16.row.col.f32.bf16.bf16.f32 "
        "{%0,%1,%2,%3}, {%4,%5,%6,%7}, {%8,%9}, {%0,%1,%2,%3};"
        : "+f"(c[0]), "+f"(c[1]), "+f"(c[2]), "+f"(c[3])
        : "r"(a[0]), "r"(a[1]), "r"(a[2]), "r"(a[3]), "r"(b0), "r"(b1));
}

__global__ __launch_bounds__(256) void xproj_mma_kernel(
    const float* __restrict__ bx,
    float* __restrict__ C)
{
    extern __shared__ char smem[];
    const uint32_t sb = smem_u32(smem);
    const int tid = threadIdx.x;
    const int wid = tid >> 5;
    const int l   = tid & 31;
    const int warp_m = wid & 3;
    const int warp_n = wid >> 2;
    const int m0 = blockIdx.x * 128;
    const int n0 = blockIdx.y * 128;

    float acc[2][8][4];
#pragma unroll
    for (int t = 0; t < 2; t++)
#pragma unroll
        for (int nb = 0; nb < 8; nb++)
#pragma unroll
            for (int i = 0; i < 4; i++) acc[t][nb][i] = 0.0f;

    const uint32_t aRowOff = (uint32_t)((warp_m * 32 + (l & 15)) * XP_STRIDE_B +
                                        (l >> 4) * 16);
    const uint32_t bRowOff = (uint32_t)((warp_n * 64 + ((l >> 4) << 3) + (l & 7)) * XP_STRIDE_B +
                                        ((l >> 3) & 1) * 16);

    for (int c = 0; c < 4; ++c) {
        const int k0 = c * 64;
#pragma unroll
        for (int q = 0; q < 4; ++q) {
            int job = q * 256 + tid;
            int row = job >> 3, kg = job & 7;
            size_t src = (size_t)(m0 + row) * DD + k0 + kg * 8;
            int off = row * XP_STRIDE_B + kg * 16;
            *(uint4*)(smem + XP_AHI + off) = *(const uint4*)(g_xhi + src);
            *(uint4*)(smem + XP_ALO + off) = *(const uint4*)(g_xlo + src);
        }
#pragma unroll
        for (int q = 0; q < 4; ++q) {
            int job = q * 256 + tid;
            int row = job >> 3, kg = job & 7;
            size_t src = (size_t)(n0 + row) * DD + k0 + kg * 8;
            int off = row * XP_STRIDE_B + kg * 16;
            *(uint4*)(smem + XP_WHI + off) = *(const uint4*)(g_whi + src);
            *(uint4*)(smem + XP_WLO + off) = *(const uint4*)(g_wlo + src);
        }
        __syncthreads();

#pragma unroll
        for (int ks = 0; ks < 4; ++ks) {
            const uint32_t kOff = (uint32_t)(ks * 32);
            uint32_t ahi[2][4], alo[2][4];
#pragma unroll
            for (int t = 0; t < 2; t++) {
                uint32_t abase = aRowOff + (uint32_t)(t * 16 * XP_STRIDE_B) + kOff;
                ldm_x4(ahi[t][0], ahi[t][1], ahi[t][2], ahi[t][3], sb + XP_AHI + abase);
                ldm_x4(alo[t][0], alo[t][1], alo[t][2], alo[t][3], sb + XP_ALO + abase);
            }
#pragma unroll
            for (int g = 0; g < 4; ++g) {
                uint32_t bbase = bRowOff + (uint32_t)(g * 16 * XP_STRIDE_B) + kOff;
                uint32_t h0, h1, h2, h3, q0, q1, q2, q3;
                ldm_x4(h0, h1, h2, h3, sb + XP_WHI + bbase);
                ldm_x4(q0, q1, q2, q3, sb + XP_WLO + bbase);
#pragma unroll
                for (int t = 0; t < 2; t++) {
                    mma16816(acc[t][2 * g],     ahi[t], h0, h1);
                    mma16816(acc[t][2 * g + 1], ahi[t], h2, h3);
                    mma16816(acc[t][2 * g],     alo[t], h0, h1);
                    mma16816(acc[t][2 * g + 1], alo[t], h2, h3);
                    mma16816(acc[t][2 * g],     ahi[t], q0, q1);
                    mma16816(acc[t][2 * g + 1], ahi[t], q2, q3);
                }
            }
        }
        __syncthreads();
    }

    const int mrow = m0 + warp_m * 32 + (l >> 2);
    const int ncol = n0 + warp_n * 64 + 2 * (l & 3);
#pragma unroll
    for (int t = 0; t < 2; t++) {
#pragma unroll
        for (int nb = 0; nb < 8; nb++) {
            int nn = ncol + nb * 8;
            float2 bv = *(const float2*)(bx + nn);
            int r0 = mrow + t * 16;
            float2 o0 = make_float2(acc[t][nb][0] + bv.x, acc[t][nb][1] + bv.y);
            float2 o1 = make_float2(acc[t][nb][2] + bv.x, acc[t][nb][3] + bv.y);
            *(float2*)(C + (size_t)r0 * HH + nn) = o0;
            *(float2*)(C + (size_t)(r0 + 8) * HH + nn) = o1;
        }
    }
}

// ====================================================================
// Kernel 2: scan v5 — lane-paired halves + shuffle combine, ONE barrier/step.
//   neuron j = tid>>1, half = tid&1 (lanes 2i/2i+1 of a warp pair up)
//   h stored padded: k[0..128) at +0, k[128..256) at +136 floats (544B)
//     -> even/odd lane LDS addresses hit disjoint bank groups (no conflict)
//   partials combined via shfl.xor(1); both lanes compute tanh;
//   even lane publishes h (ping-pong smem), odd lane writes global out.
//   96 k-weights in regs (f32x2 packed), 32 in smem; xp prefetched 1 step.
// ====================================================================
#define HPAD 264   // 128 + 8 + 128 floats per h snapshot

__global__ __launch_bounds__(512, 1) void scan_kernel(
    const float* __restrict__ h0,
    const float* __restrict__ Wh,
    const float* __restrict__ bh,
    float* __restrict__ out,
    int hasFinal)
{
    extern __shared__ float smemf[];
    float4* Wsm  = (float4*)smemf;           // [8][512] float4 = 64 KB
    float*  hbuf = smemf + 8 * 512 * 4;      // 2 * HPAD floats (ping-pong)

    const int tid  = threadIdx.x;
    const int j    = tid >> 1;
    const int half = tid & 1;
    const int b    = blockIdx.x;
    const int kb   = half * 128;

    // register-resident weights: k in [kb, kb+96) as 48 packed f32x2 pairs
    ulonglong2 wu[24];
    const ulonglong2* wrow = (const ulonglong2*)(Wh + (size_t)j * HH + kb);
#pragma unroll
    for (int i = 0; i < 24; i++) wu[i] = wrow[i];

    // smem weights: k in [kb+96, kb+128), laid out [g][tid] (conflict-free)
    const float4* wrow4 = (const float4*)(Wh + (size_t)j * HH + kb);
#pragma unroll
    for (int g = 0; g < 8; ++g)
        Wsm[g * 512 + tid] = wrow4[24 + g];

    // h0 into padded layout
    if (tid < 256) {
        int pos = tid + ((tid >> 7) << 3);   // +8 pad for upper half
        hbuf[pos] = h0[(size_t)b * HH + tid];
    }
    const float bh_r = bh[j];
    float* const outp = out + (size_t)b * HH + j;   // step stride BB*HH

    float xp_next = outp[0];
    __syncthreads();

    const int hpos = j + ((j >> 7) << 3);    // padded write position for h
    int cur = 0;
    for (int t = 0; t < LL; ++t) {
        const float xp = xp_next;
        if (t + 1 < LL) xp_next = outp[(size_t)(t + 1) * (BB * HH)];

        const ulonglong2* h2 = (const ulonglong2*)(hbuf + cur * HPAD + half * 136);
        unsigned long long p0 = 0ULL, p1 = 0ULL, p2 = 0ULL, p3 = 0ULL;
#pragma unroll
        for (int i = 0; i < 24; i++) {
            ulonglong2 hv = h2[i];
            p0 = ffma2(wu[i].x, hv.x, p0);
            p1 = ffma2(wu[i].y, hv.y, p1);
        }
        const ulonglong2* ws2 = (const ulonglong2*)Wsm;
#pragma unroll
        for (int g = 0; g < 8; g++) {
            ulonglong2 wv = ws2[(size_t)g * 512 + tid];
            ulonglong2 hv = h2[24 + g];
            p2 = ffma2(wv.x, hv.x, p2);
            p3 = ffma2(wv.y, hv.y, p3);
        }
        float acc = (upk_sum(p0) + upk_sum(p1)) + (upk_sum(p2) + upk_sum(p3));
        float other = __shfl_xor_sync(0xFFFFFFFFu, acc, 1);
        float hn = tanhf(acc + other + xp + bh_r);

        if (!half) {
            hbuf[(cur ^ 1) * HPAD + hpos] = hn;
        } else {
            outp[(size_t)t * (BB * HH)] = hn;
            if (hasFinal && t == LL - 1)
                outp[(size_t)LL * (BB * HH)] = hn;
        }
        __syncthreads();
        cur ^= 1;
    }
}

// ====================================================================
// launch
// ====================================================================
extern "C" void kernel_launch(void* const* d_in, const int* in_sizes, int n_in,
                              void* d_out, int out_size)
{
    const float* x   = (const float*)d_in[0];
    const float* h0  = (const float*)d_in[1];
    const float* Wxw = (const float*)d_in[2];
    const float* Wxb = (const float*)d_in[3];
    const float* Whw = (const float*)d_in[4];
    const float* Whb = (const float*)d_in[5];
    float* out = (float*)d_out;

    (void)in_sizes; (void)n_in;

    cudaFuncSetAttribute(xproj_mma_kernel, cudaFuncAttributeMaxDynamicSharedMemorySize, XP_SMEM);
    const int smemScan = (8 * 512 * 4 + 2 * HPAD) * (int)sizeof(float);   // 67648
    cudaFuncSetAttribute(scan_kernel, cudaFuncAttributeMaxDynamicSharedMemorySize, smemScan);

    convert_kernel<<<(CV_JOBS + 255) / 256, 256>>>(x, Wxw);

    dim3 g1(LL * BB / 128, HH / 128);   // (1024, 2)
    xproj_mma_kernel<<<g1, 256, XP_SMEM>>>(Wxb, out);

    const int hasFinal = (out_size >= LL * BB * HH + BB * HH) ? 1 : 0;
    scan_kernel<<<BB, 512, smemScan>>>(h0, Whw, Whb, out, hasFinal);
}